// round 2
// baseline (speedup 1.0000x reference)
#include <cuda_runtime.h>
#include <stdint.h>

// TopK_31877247271346: per-row top-64 of x[4096][16384] fp32, scattered into zeros.
// One CTA per row. Row cached in SMEM as order-preserving u32 keys; exact
// threshold found via MSB-first 8-bit radix select; stable (lowest-index)
// tie-break at the threshold to match jax.lax.top_k semantics.

#define NROWS    4096
#define NCOLS    16384
#define KSEL     64
#define NTHREADS 256
#define SMEM_DYN (NCOLS * 4)   // 64 KB of u32 keys

__device__ __forceinline__ uint32_t f2key(uint32_t a) {
    // order-preserving transform: bigger float -> bigger uint
    return (a & 0x80000000u) ? ~a : (a | 0x80000000u);
}
__device__ __forceinline__ float key2f(uint32_t u) {
    return __uint_as_float((u & 0x80000000u) ? (u ^ 0x80000000u) : ~u);
}

__global__ void __launch_bounds__(NTHREADS)
topk_scatter_kernel(const float* __restrict__ x, float* __restrict__ out)
{
    extern __shared__ uint32_t s[];       // NCOLS sortable keys
    __shared__ uint32_t hist[256];
    __shared__ uint32_t bcast[4];         // 0: prefix, 1: remK, 2: cntEq, 3: tieCut
    __shared__ uint32_t tieIdx[256];
    __shared__ uint32_t tieCnt;

    const int tid = threadIdx.x;
    const size_t rowOff = (size_t)blockIdx.x * NCOLS;
    const float4* __restrict__ xrow = reinterpret_cast<const float4*>(x + rowOff);
    float4* __restrict__ orow = reinterpret_cast<float4*>(out + rowOff);
    uint4* s4 = reinterpret_cast<uint4*>(s);

    // ---- Pass 1: load row, transform to sortable keys, stash in SMEM ----
    #pragma unroll 4
    for (int j = tid; j < NCOLS / 4; j += NTHREADS) {
        float4 v = xrow[j];
        uint4 u;
        u.x = f2key(__float_as_uint(v.x));
        u.y = f2key(__float_as_uint(v.y));
        u.z = f2key(__float_as_uint(v.z));
        u.w = f2key(__float_as_uint(v.w));
        s4[j] = u;
    }
    __syncthreads();

    // ---- Radix select: find exact key T of the K-th largest ----
    uint32_t prefix = 0;
    uint32_t remK   = KSEL;
    uint32_t cntEq  = 0;

    #pragma unroll 1
    for (int shift = 24; shift >= 0; shift -= 8) {
        const uint32_t pmask = (shift == 24) ? 0u : (0xFFFFFFFFu << (shift + 8));
        hist[tid] = 0;
        __syncthreads();

        for (int j = tid; j < NCOLS; j += NTHREADS) {
            uint32_t u = s[j];
            if ((u & pmask) == prefix)
                atomicAdd(&hist[(u >> shift) & 255u], 1u);
        }
        __syncthreads();

        // parallel suffix (from-top) inclusive scan over 256 buckets
        #pragma unroll
        for (int d = 1; d < 256; d <<= 1) {
            uint32_t v = hist[tid] + ((tid + d < 256) ? hist[tid + d] : 0u);
            __syncthreads();
            hist[tid] = v;
            __syncthreads();
        }

        uint32_t inc = hist[tid];                         // count of keys >= bucket tid
        uint32_t abv = (tid < 255) ? hist[tid + 1] : 0u;  // count of keys >  bucket tid
        if (inc >= remK && abv < remK) {                  // exactly one thread matches
            bcast[0] = prefix | ((uint32_t)tid << shift);
            bcast[1] = remK - abv;
            bcast[2] = inc - abv;
        }
        __syncthreads();
        prefix = bcast[0];
        remK   = bcast[1];
        cntEq  = bcast[2];
        __syncthreads();
    }

    const uint32_t T = prefix;   // exact 32-bit key of the K-th largest element

    // ---- Tie resolution (stable, lowest-index-first, matches lax.top_k) ----
    if (tid == 0) { tieCnt = 0; bcast[3] = 0xFFFFFFFFu; }
    __syncthreads();

    if (cntEq != remK) {
        // more elements equal T than we may keep: keep the remK smallest column indices
        for (int j = tid; j < NCOLS; j += NTHREADS) {
            if (s[j] == T) {
                uint32_t p = atomicAdd(&tieCnt, 1u);
                if (p < 256) tieIdx[p] = (uint32_t)j;
            }
        }
        __syncthreads();
        if (tid == 0) {
            uint32_t n = tieCnt;
            if (n > 256) n = 256;
            int last = -1;
            for (uint32_t r = 0; r < remK; r++) {
                uint32_t mn = 0xFFFFFFFFu;
                for (uint32_t i = 0; i < n; i++) {
                    uint32_t v = tieIdx[i];
                    if ((int)v > last && v < mn) mn = v;
                }
                last = (int)mn;
            }
            bcast[3] = (uint32_t)last;   // keep ties with col <= tieCut
        }
        __syncthreads();
    }
    const uint32_t tieCut = bcast[3];

    // ---- Pass 2: write output (single global write, rest zero) ----
    #pragma unroll 4
    for (int j = tid; j < NCOLS / 4; j += NTHREADS) {
        uint4 u = s4[j];
        const uint32_t col = (uint32_t)j * 4u;
        float4 o;
        o.x = (u.x > T || (u.x == T && (col + 0u) <= tieCut)) ? key2f(u.x) : 0.0f;
        o.y = (u.y > T || (u.y == T && (col + 1u) <= tieCut)) ? key2f(u.y) : 0.0f;
        o.z = (u.z > T || (u.z == T && (col + 2u) <= tieCut)) ? key2f(u.z) : 0.0f;
        o.w = (u.w > T || (u.w == T && (col + 3u) <= tieCut)) ? key2f(u.w) : 0.0f;
        orow[j] = o;
    }
}

extern "C" void kernel_launch(void* const* d_in, const int* in_sizes, int n_in,
                              void* d_out, int out_size)
{
    const float* x = (const float*)d_in[0];
    float* out = (float*)d_out;
    (void)in_sizes; (void)n_in; (void)out_size;

    // idempotent; required for 64 KB dynamic smem
    cudaFuncSetAttribute(topk_scatter_kernel,
                         cudaFuncAttributeMaxDynamicSharedMemorySize, SMEM_DYN);

    topk_scatter_kernel<<<NROWS, NTHREADS, SMEM_DYN>>>(x, out);
}

// round 3
// speedup vs baseline: 1.0144x; 1.0144x over previous
#include <cuda_runtime.h>
#include <stdint.h>

// TopK_31877247271346: per-row top-64 of x[4096][16384] fp32 scattered into zeros.
// One CTA (512 threads) per row; row held in REGISTERS (32 keys/thread).
// MSB-first 8-bit radix select; round-1 histogram uses match_any-aggregated
// shared atomics; bucket pick via warp-0 shfl suffix scan; exact stable
// tie-break via block binary search on the column cut.

#define NROWS    4096
#define NCOLS    16384
#define KSEL     64
#define NT       512
#define VPT      8            // float4 vectors per thread
#define EPT      32           // elements per thread

__device__ __forceinline__ uint32_t f2key(uint32_t a) {
    return (a & 0x80000000u) ? ~a : (a | 0x80000000u);
}
__device__ __forceinline__ float key2f(uint32_t u) {
    return __uint_as_float((u & 0x80000000u) ? (u ^ 0x80000000u) : ~u);
}

__global__ void __launch_bounds__(NT, 2)
topk_scatter_kernel(const float* __restrict__ x, float* __restrict__ out)
{
    __shared__ uint32_t hist[256];
    __shared__ uint32_t bcast[3];   // 0: prefix, 1: remK, 2: cntEq
    __shared__ uint32_t blkCnt;

    const int tid  = threadIdx.x;
    const int lane = tid & 31;
    const size_t rowOff = (size_t)blockIdx.x * NCOLS;
    const float4* __restrict__ xrow = reinterpret_cast<const float4*>(x + rowOff);
    float4* __restrict__ orow = reinterpret_cast<float4*>(out + rowOff);

    if (tid < 256) hist[tid] = 0;

    // ---- Load row into registers (8x LDG.128 issued back-to-back: high MLP) ----
    float4 v[VPT];
    #pragma unroll
    for (int i = 0; i < VPT; i++) v[i] = xrow[tid + i * NT];

    uint32_t key[EPT];
    #pragma unroll
    for (int i = 0; i < VPT; i++) {
        key[i*4 + 0] = f2key(__float_as_uint(v[i].x));
        key[i*4 + 1] = f2key(__float_as_uint(v[i].y));
        key[i*4 + 2] = f2key(__float_as_uint(v[i].z));
        key[i*4 + 3] = f2key(__float_as_uint(v[i].w));
    }
    __syncthreads();   // hist zeroed

    // ---- Round-1 histogram of top byte, warp-aggregated ----
    #pragma unroll
    for (int e = 0; e < EPT; e++) {
        uint32_t b = key[e] >> 24;
        uint32_t m = __match_any_sync(0xFFFFFFFFu, b);
        if ((m & ((1u << lane) - 1u)) == 0u)       // lowest lane in match group
            atomicAdd(&hist[b], (uint32_t)__popc(m));
    }
    __syncthreads();

    // ---- 4 radix rounds ----
    uint32_t prefix = 0, remK = KSEL, cntEq = 0;

    #pragma unroll 1
    for (int shift = 24; shift >= 0; shift -= 8) {
        if (shift != 24) {
            const uint32_t pmask = 0xFFFFFFFFu << (shift + 8);
            #pragma unroll
            for (int e = 0; e < EPT; e++)
                if ((key[e] & pmask) == prefix)
                    atomicAdd(&hist[(key[e] >> shift) & 255u], 1u);
            __syncthreads();
        }

        // warp 0: suffix scan over 256 buckets, select, re-zero hist
        if (tid < 32) {
            uint32_t local[8], sum = 0;
            #pragma unroll
            for (int j = 0; j < 8; j++) { local[j] = hist[lane*8 + j]; sum += local[j]; }
            #pragma unroll
            for (int j = 0; j < 8; j++) hist[lane*8 + j] = 0;   // ready for next round

            uint32_t tot = sum;                                  // inclusive suffix scan of lane sums
            #pragma unroll
            for (int off = 1; off < 32; off <<= 1) {
                uint32_t t = __shfl_down_sync(0xFFFFFFFFu, tot, off);
                if (lane + off < 32) tot += t;
            }
            uint32_t run = tot - sum;                            // count in strictly-higher lanes
            #pragma unroll
            for (int j = 7; j >= 0; j--) {                       // top bucket downward
                uint32_t inc = run + local[j];
                if (inc >= remK && run < remK) {                 // unique (lane,j)
                    bcast[0] = prefix | ((uint32_t)(lane*8 + j) << shift);
                    bcast[1] = remK - run;
                    bcast[2] = local[j];
                }
                run = inc;
            }
        }
        __syncthreads();
        prefix = bcast[0];
        remK   = bcast[1];
        cntEq  = bcast[2];
    }

    const uint32_t T = prefix;      // exact key of the K-th largest

    // ---- Exact stable tie-break (rare path): smallest column cut c with
    //      count(key==T && col<=c) == remK, via block binary search ----
    uint32_t tieCut = 0xFFFFFFFFu;
    if (cntEq != remK) {            // cntEq > remK: excess ties
        int lo = 0, hi = NCOLS - 1;
        while (lo < hi) {
            int mid = (lo + hi) >> 1;
            if (tid == 0) blkCnt = 0;
            __syncthreads();
            uint32_t c = 0;
            #pragma unroll
            for (int e = 0; e < EPT; e++) {
                int col = tid*4 + (e >> 2)*(NT*4) + (e & 3);
                c += (key[e] == T && col <= mid) ? 1u : 0u;
            }
            #pragma unroll
            for (int off = 16; off >= 1; off >>= 1)
                c += __shfl_down_sync(0xFFFFFFFFu, c, off);
            if (lane == 0 && c) atomicAdd(&blkCnt, c);
            __syncthreads();
            uint32_t total = blkCnt;
            if (total >= remK) hi = mid; else lo = mid + 1;
            __syncthreads();        // everyone done reading blkCnt before re-zero
        }
        tieCut = (uint32_t)lo;
    }

    // ---- Write output (only global write; rest zeros) ----
    #pragma unroll
    for (int i = 0; i < VPT; i++) {
        const uint32_t col = (uint32_t)(tid + i * NT) * 4u;
        float4 o;
        uint32_t u0 = key[i*4+0], u1 = key[i*4+1], u2 = key[i*4+2], u3 = key[i*4+3];
        o.x = (u0 > T || (u0 == T && (col + 0u) <= tieCut)) ? key2f(u0) : 0.0f;
        o.y = (u1 > T || (u1 == T && (col + 1u) <= tieCut)) ? key2f(u1) : 0.0f;
        o.z = (u2 > T || (u2 == T && (col + 2u) <= tieCut)) ? key2f(u2) : 0.0f;
        o.w = (u3 > T || (u3 == T && (col + 3u) <= tieCut)) ? key2f(u3) : 0.0f;
        orow[tid + i * NT] = o;
    }
}

extern "C" void kernel_launch(void* const* d_in, const int* in_sizes, int n_in,
                              void* d_out, int out_size)
{
    const float* x = (const float*)d_in[0];
    float* out = (float*)d_out;
    (void)in_sizes; (void)n_in; (void)out_size;

    topk_scatter_kernel<<<NROWS, NT>>>(x, out);
}

// round 4
// speedup vs baseline: 1.0726x; 1.0573x over previous
#include <cuda_runtime.h>
#include <stdint.h>

// TopK_31877247271346: per-row top-64 of x[4096][16384] fp32 scattered into zeros.
// One CTA (512 threads) per row; row in registers (32 keys/thread).
// Threshold byte via dp4a-count binary search (no histogram atomics);
// candidates (~400) compacted to SMEM; exact 3-round radix over candidates;
// stable lowest-index tie-break; register fallback for adversarial data.

#define NROWS 4096
#define NCOLS 16384
#define KSEL  64
#define NT    512
#define VPT   8
#define EPT   32
#define CAP   2048

__device__ __forceinline__ uint32_t f2key(uint32_t a) {
    return (a & 0x80000000u) ? ~a : (a | 0x80000000u);
}
__device__ __forceinline__ float key2f(uint32_t u) {
    return __uint_as_float((u & 0x80000000u) ? (u ^ 0x80000000u) : ~u);
}

__global__ void __launch_bounds__(NT, 2)
topk_scatter_kernel(const float* __restrict__ x, float* __restrict__ out)
{
    __shared__ uint32_t hist[256];
    __shared__ uint32_t bcast[3];        // prefix, remK, cntEq
    __shared__ uint32_t probeCnt[16];    // one slot per probe iteration
    __shared__ uint32_t nCandS;
    __shared__ uint32_t skey[CAP];
    __shared__ uint16_t scol[CAP];

    const int tid  = threadIdx.x;
    const int lane = tid & 31;
    const size_t rowOff = (size_t)blockIdx.x * NCOLS;
    const float4* __restrict__ xrow = reinterpret_cast<const float4*>(x + rowOff);
    float4* __restrict__ orow = reinterpret_cast<float4*>(out + rowOff);

    if (tid < 256) hist[tid] = 0;
    if (tid < 16)  probeCnt[tid] = 0;
    if (tid == 0)  nCandS = 0;

    // ---- Load row into registers (8x LDG.128 back-to-back) ----
    float4 v[VPT];
    #pragma unroll
    for (int i = 0; i < VPT; i++) v[i] = xrow[tid + i * NT];

    uint32_t key[EPT];
    #pragma unroll
    for (int i = 0; i < VPT; i++) {
        key[i*4 + 0] = f2key(__float_as_uint(v[i].x));
        key[i*4 + 1] = f2key(__float_as_uint(v[i].y));
        key[i*4 + 2] = f2key(__float_as_uint(v[i].z));
        key[i*4 + 3] = f2key(__float_as_uint(v[i].w));
    }

    // pack top bytes: pb[i] holds top bytes of keys 4i..4i+3
    uint32_t pb[8];
    #pragma unroll
    for (int i = 0; i < 8; i++) {
        uint32_t p01 = __byte_perm(key[4*i + 0], key[4*i + 1], 0x0073);
        uint32_t p23 = __byte_perm(key[4*i + 2], key[4*i + 3], 0x0073);
        pb[i] = __byte_perm(p01, p23, 0x5410);
    }
    __syncthreads();

    // ---- Phase A: binary search the threshold top byte b ----
    // invariant: cnt(topbyte >= lo) >= K  >  cnt(topbyte >= hi)
    int lo = 0, hi = 256;
    uint32_t cntLo = NCOLS, cntHi = 0;
    int it = 0;
    while (hi - lo > 1) {                      // 8 iterations
        const int mid = (lo + hi) >> 1;
        const uint32_t probe4 = (uint32_t)mid * 0x01010101u;
        uint32_t c = 0;
        #pragma unroll
        for (int i = 0; i < 8; i++)
            c = __dp4a(__vsetgeu4(pb[i], probe4), 0x01010101u, c);
        #pragma unroll
        for (int off = 16; off >= 1; off >>= 1)
            c += __shfl_down_sync(0xFFFFFFFFu, c, off);
        if (lane == 0 && c) atomicAdd(&probeCnt[it], c);
        __syncthreads();
        const uint32_t tot = probeCnt[it];     // distinct slot/iter: 1 barrier/probe
        if (tot >= KSEL) { lo = mid; cntLo = tot; }
        else             { hi = mid; cntHi = tot; }
        it++;
    }

    const uint32_t b   = (uint32_t)lo;
    const uint32_t abv = cntHi;                // count with topbyte > b
    const uint32_t nc  = cntLo;                // count with topbyte >= b (candidates)
    const bool useS = (nc <= CAP);

    uint32_t prefix = b << 24;
    uint32_t remK   = KSEL - abv;
    uint32_t cntEq  = 0;

    // ---- Phase B: compact candidates into SMEM (common path) ----
    if (useS) {
        const uint32_t thr = b << 24;
        #pragma unroll
        for (int e = 0; e < EPT; e++) {
            const bool p = key[e] >= thr;
            const uint32_t m = __ballot_sync(0xFFFFFFFFu, p);
            if (m) {
                const int leader = __ffs(m) - 1;
                uint32_t base = 0;
                if (lane == leader) base = atomicAdd(&nCandS, (uint32_t)__popc(m));
                base = __shfl_sync(0xFFFFFFFFu, base, leader);
                if (p) {
                    const uint32_t idx = base + __popc(m & ((1u << lane) - 1u));
                    const int i = e >> 2, c4 = e & 3;
                    skey[idx] = key[e];
                    scol[idx] = (uint16_t)((tid + i * NT) * 4 + c4);
                }
            }
        }
        __syncthreads();
    }

    // ---- Phase C: exact radix over remaining 24 bits ----
    #pragma unroll 1
    for (int shift = 16; shift >= 0; shift -= 8) {
        const uint32_t pmask = 0xFFFFFFFFu << (shift + 8);
        if (useS) {
            for (int j = tid; j < (int)nc; j += NT) {
                const uint32_t u = skey[j];
                if ((u & pmask) == prefix)
                    atomicAdd(&hist[(u >> shift) & 255u], 1u);
            }
        } else {   // fallback: predicated atomics over register keys
            #pragma unroll
            for (int e = 0; e < EPT; e++)
                if ((key[e] & pmask) == prefix)
                    atomicAdd(&hist[(key[e] >> shift) & 255u], 1u);
        }
        __syncthreads();

        if (tid < 32) {   // warp 0: suffix scan over 256 buckets, pick, re-zero
            uint32_t local[8], sum = 0;
            #pragma unroll
            for (int j = 0; j < 8; j++) { local[j] = hist[lane*8 + j]; sum += local[j]; }
            #pragma unroll
            for (int j = 0; j < 8; j++) hist[lane*8 + j] = 0;

            uint32_t tot = sum;
            #pragma unroll
            for (int off = 1; off < 32; off <<= 1) {
                uint32_t t = __shfl_down_sync(0xFFFFFFFFu, tot, off);
                if (lane + off < 32) tot += t;
            }
            uint32_t run = tot - sum;          // strictly-higher-lane count
            #pragma unroll
            for (int j = 7; j >= 0; j--) {
                const uint32_t inc = run + local[j];
                if (inc >= remK && run < remK) {
                    bcast[0] = prefix | ((uint32_t)(lane*8 + j) << shift);
                    bcast[1] = remK - run;
                    bcast[2] = local[j];
                }
                run = inc;
            }
        }
        __syncthreads();
        prefix = bcast[0];
        remK   = bcast[1];
        cntEq  = bcast[2];
        __syncthreads();
    }

    const uint32_t T = prefix;

    // ---- Tie-break (rare): smallest col cut with count(==T, col<=cut)==remK ----
    uint32_t tieCut = 0xFFFFFFFFu;
    if (cntEq != remK) {
        if (tid < 16) probeCnt[tid] = 0;
        __syncthreads();
        int tlo = 0, thi = NCOLS - 1, ti = 0;
        while (tlo < thi) {                    // 14 iterations max
            const int mid = (tlo + thi) >> 1;
            uint32_t c = 0;
            #pragma unroll
            for (int e = 0; e < EPT; e++) {
                const int i = e >> 2, c4 = e & 3;
                const int col = (tid + i * NT) * 4 + c4;
                c += (key[e] == T && col <= mid) ? 1u : 0u;
            }
            #pragma unroll
            for (int off = 16; off >= 1; off >>= 1)
                c += __shfl_down_sync(0xFFFFFFFFu, c, off);
            if (lane == 0 && c) atomicAdd(&probeCnt[ti & 15], c);
            __syncthreads();
            const uint32_t tot = probeCnt[ti & 15];
            if (tot >= remK) thi = mid; else tlo = mid + 1;
            ti++;
            if ((ti & 15) == 0) {              // wrap (only if >16 iters; never here)
                __syncthreads();
                if (tid < 16) probeCnt[tid] = 0;
                __syncthreads();
            }
        }
        tieCut = (uint32_t)tlo;
    }

    // ---- Write output (only global write; rest zeros) ----
    #pragma unroll
    for (int i = 0; i < VPT; i++) {
        const uint32_t col = (uint32_t)(tid + i * NT) * 4u;
        const uint32_t u0 = key[i*4+0], u1 = key[i*4+1];
        const uint32_t u2 = key[i*4+2], u3 = key[i*4+3];
        float4 o;
        o.x = (u0 > T || (u0 == T && (col + 0u) <= tieCut)) ? key2f(u0) : 0.0f;
        o.y = (u1 > T || (u1 == T && (col + 1u) <= tieCut)) ? key2f(u1) : 0.0f;
        o.z = (u2 > T || (u2 == T && (col + 2u) <= tieCut)) ? key2f(u2) : 0.0f;
        o.w = (u3 > T || (u3 == T && (col + 3u) <= tieCut)) ? key2f(u3) : 0.0f;
        orow[tid + i * NT] = o;
    }
}

extern "C" void kernel_launch(void* const* d_in, const int* in_sizes, int n_in,
                              void* d_out, int out_size)
{
    const float* x = (const float*)d_in[0];
    float* out = (float*)d_out;
    (void)in_sizes; (void)n_in; (void)out_size;

    topk_scatter_kernel<<<NROWS, NT>>>(x, out);
}

// round 5
// speedup vs baseline: 1.5018x; 1.4001x over previous
#include <cuda_runtime.h>
#include <stdint.h>

// TopK_31877247271346: per-row top-64 of x[4096][16384] fp32 scattered into zeros.
// One CTA (512 threads) per row. Streaming design: row is never stored on-chip.
//  - read row once (transient regs), issue full-row ZERO stores immediately
//  - compact candidates (x >= 2.0, ~373 expected) into SMEM via ballot
//  - exact 4-round radix over candidates -> threshold key T
//  - stable lowest-index tie-break over candidates
//  - scatter <=64 winners over the zeros (ordered by __syncthreads)
// Exact fallback via global re-reads if candidate count outside [K, CAP].

#define NROWS 4096
#define NCOLS 16384
#define KSEL  64
#define NT    512
#define VPT   8            // float4 per thread
#define CAP   2048
#define KEYTHR 0xC0000000u // f2key(2.0f)

__device__ __forceinline__ uint32_t f2key(uint32_t a) {
    return (a & 0x80000000u) ? ~a : (a | 0x80000000u);
}
__device__ __forceinline__ float key2f(uint32_t u) {
    return __uint_as_float((u & 0x80000000u) ? (u ^ 0x80000000u) : ~u);
}

__global__ void __launch_bounds__(NT, 3)
topk_scatter_kernel(const float* __restrict__ x, float* __restrict__ out)
{
    __shared__ uint32_t hist[256];
    __shared__ uint32_t bcast[3];     // prefix, remK, cntEq
    __shared__ uint32_t slot[32];     // per-iteration counters
    __shared__ uint32_t nCandS;
    __shared__ uint32_t skey[CAP];
    __shared__ uint16_t scol[CAP];

    const int tid  = threadIdx.x;
    const int lane = tid & 31;
    const size_t rowOff = (size_t)blockIdx.x * NCOLS;
    const float4* __restrict__ xrow = reinterpret_cast<const float4*>(x + rowOff);
    float4* __restrict__ orow = reinterpret_cast<float4*>(out + rowOff);

    if (tid < 256) hist[tid] = 0;
    if (tid < 32)  slot[tid] = 0;
    if (tid == 0)  nCandS = 0;
    __syncthreads();

    const float4 z4 = make_float4(0.f, 0.f, 0.f, 0.f);

    // ---- Stream row: load, zero-store, compact candidates (2 batches) ----
    #pragma unroll
    for (int b = 0; b < 2; b++) {
        float4 v[4];
        #pragma unroll
        for (int i = 0; i < 4; i++) v[i] = xrow[tid + (b*4 + i) * NT];
        if (b == 0) {                           // all 8 zero stores up front
            #pragma unroll
            for (int i = 0; i < VPT; i++) orow[tid + i * NT] = z4;
        }
        #pragma unroll
        for (int i = 0; i < 4; i++) {
            const uint32_t kk[4] = { f2key(__float_as_uint(v[i].x)),
                                     f2key(__float_as_uint(v[i].y)),
                                     f2key(__float_as_uint(v[i].z)),
                                     f2key(__float_as_uint(v[i].w)) };
            #pragma unroll
            for (int c = 0; c < 4; c++) {
                const bool p = kk[c] >= KEYTHR;
                const uint32_t m = __ballot_sync(0xFFFFFFFFu, p);
                if (m) {
                    const int leader = __ffs(m) - 1;
                    uint32_t base = 0;
                    if (lane == leader) base = atomicAdd(&nCandS, (uint32_t)__popc(m));
                    base = __shfl_sync(0xFFFFFFFFu, base, leader);
                    if (p) {
                        const uint32_t idx = base + __popc(m & ((1u << lane) - 1u));
                        if (idx < CAP) {
                            skey[idx] = kk[c];
                            scol[idx] = (uint16_t)((tid + (b*4 + i) * NT) * 4 + c);
                        }
                    }
                }
            }
        }
    }
    __syncthreads();
    const uint32_t nc = nCandS;

    if (nc >= KSEL && nc <= CAP) {
        // ---- Exact radix over candidates (4 rounds of 8 bits) ----
        uint32_t prefix = 0, remK = KSEL, cntEq = 0;
        #pragma unroll 1
        for (int shift = 24; shift >= 0; shift -= 8) {
            const uint32_t pmask = (shift == 24) ? 0u : (0xFFFFFFFFu << (shift + 8));
            for (int j = tid; j < (int)nc; j += NT) {
                const uint32_t u = skey[j];
                if ((u & pmask) == prefix)
                    atomicAdd(&hist[(u >> shift) & 255u], 1u);
            }
            __syncthreads();

            if (tid < 32) {   // warp 0: suffix scan over 256 buckets, pick, re-zero
                uint32_t local[8], sum = 0;
                #pragma unroll
                for (int j = 0; j < 8; j++) { local[j] = hist[lane*8 + j]; sum += local[j]; }
                #pragma unroll
                for (int j = 0; j < 8; j++) hist[lane*8 + j] = 0;

                uint32_t tot = sum;
                #pragma unroll
                for (int off = 1; off < 32; off <<= 1) {
                    uint32_t t = __shfl_down_sync(0xFFFFFFFFu, tot, off);
                    if (lane + off < 32) tot += t;
                }
                uint32_t run = tot - sum;
                #pragma unroll
                for (int j = 7; j >= 0; j--) {
                    const uint32_t inc = run + local[j];
                    if (inc >= remK && run < remK) {
                        bcast[0] = prefix | ((uint32_t)(lane*8 + j) << shift);
                        bcast[1] = remK - run;
                        bcast[2] = local[j];
                    }
                    run = inc;
                }
            }
            __syncthreads();
            prefix = bcast[0];
            remK   = bcast[1];
            cntEq  = bcast[2];
            __syncthreads();
        }
        const uint32_t T = prefix;

        // ---- Stable tie-break over candidates (rare) ----
        uint32_t tieCut = 0xFFFFFFFFu;
        if (cntEq != remK) {
            int lo = 0, hi = NCOLS - 1, it = 0;
            while (lo < hi) {                 // <= 14 iterations, slots pre-zeroed
                const int mid = (lo + hi) >> 1;
                uint32_t c = 0;
                for (int j = tid; j < (int)nc; j += NT)
                    c += (skey[j] == T && (int)scol[j] <= mid) ? 1u : 0u;
                #pragma unroll
                for (int off = 16; off >= 1; off >>= 1)
                    c += __shfl_down_sync(0xFFFFFFFFu, c, off);
                if (lane == 0 && c) atomicAdd(&slot[it], c);
                __syncthreads();
                if (slot[it] >= remK) hi = mid; else lo = mid + 1;
                it++;
            }
            tieCut = (uint32_t)lo;
        }

        // ---- Scatter winners (zero stores of this CTA already ordered) ----
        for (int j = tid; j < (int)nc; j += NT) {
            const uint32_t u = skey[j];
            const uint32_t col = scol[j];
            if (u > T || (u == T && col <= tieCut))
                out[rowOff + col] = key2f(u);
        }
        return;
    }

    // ================= FALLBACK (exact, via global re-reads; ~never) =========
    {
        __syncthreads();
        if (tid < 32) slot[tid] = 0;
        __syncthreads();

        // 32-step binary search for T: largest t with cnt(key >= t) >= K
        unsigned long long blo = 0ull, bhi = 0x100000000ull;
        int it = 0;
        while (bhi - blo > 1ull) {
            const uint32_t mid = (uint32_t)((blo + bhi) >> 1);
            uint32_t c = 0;
            for (int i = 0; i < VPT; i++) {
                float4 v = xrow[tid + i * NT];
                c += (f2key(__float_as_uint(v.x)) >= mid);
                c += (f2key(__float_as_uint(v.y)) >= mid);
                c += (f2key(__float_as_uint(v.z)) >= mid);
                c += (f2key(__float_as_uint(v.w)) >= mid);
            }
            #pragma unroll
            for (int off = 16; off >= 1; off >>= 1)
                c += __shfl_down_sync(0xFFFFFFFFu, c, off);
            if (lane == 0 && c) atomicAdd(&slot[it & 31], c);
            __syncthreads();
            if (slot[it & 31] >= KSEL) blo = (unsigned long long)mid;
            else                       bhi = (unsigned long long)mid;
            it++;
            if ((it & 31) == 0) {
                __syncthreads();
                if (tid < 32) slot[tid] = 0;
                __syncthreads();
            }
        }
        const uint32_t T = (uint32_t)blo;

        // abv = cnt(key > T), eq = cnt(key == T)
        __syncthreads();
        if (tid < 32) slot[tid] = 0;
        __syncthreads();
        {
            uint32_t ca = 0, ce = 0;
            for (int i = 0; i < VPT; i++) {
                float4 v = xrow[tid + i * NT];
                const uint32_t k0 = f2key(__float_as_uint(v.x));
                const uint32_t k1 = f2key(__float_as_uint(v.y));
                const uint32_t k2 = f2key(__float_as_uint(v.z));
                const uint32_t k3 = f2key(__float_as_uint(v.w));
                ca += (k0 > T) + (k1 > T) + (k2 > T) + (k3 > T);
                ce += (k0 == T) + (k1 == T) + (k2 == T) + (k3 == T);
            }
            #pragma unroll
            for (int off = 16; off >= 1; off >>= 1) {
                ca += __shfl_down_sync(0xFFFFFFFFu, ca, off);
                ce += __shfl_down_sync(0xFFFFFFFFu, ce, off);
            }
            if (lane == 0) { atomicAdd(&slot[0], ca); atomicAdd(&slot[1], ce); }
        }
        __syncthreads();
        const uint32_t abv  = slot[0];
        const uint32_t eq   = slot[1];
        const uint32_t remK = KSEL - abv;

        uint32_t tieCut = 0xFFFFFFFFu;
        if (eq != remK) {
            __syncthreads();
            if (tid < 32) slot[tid] = 0;
            __syncthreads();
            int lo = 0, hi = NCOLS - 1, ti = 0;
            while (lo < hi) {                 // <= 14 iterations
                const int mid = (lo + hi) >> 1;
                uint32_t c = 0;
                for (int i = 0; i < VPT; i++) {
                    float4 v = xrow[tid + i * NT];
                    const int col0 = (tid + i * NT) * 4;
                    c += (f2key(__float_as_uint(v.x)) == T && col0 + 0 <= mid);
                    c += (f2key(__float_as_uint(v.y)) == T && col0 + 1 <= mid);
                    c += (f2key(__float_as_uint(v.z)) == T && col0 + 2 <= mid);
                    c += (f2key(__float_as_uint(v.w)) == T && col0 + 3 <= mid);
                }
                #pragma unroll
                for (int off = 16; off >= 1; off >>= 1)
                    c += __shfl_down_sync(0xFFFFFFFFu, c, off);
                if (lane == 0 && c) atomicAdd(&slot[ti & 31], c);
                __syncthreads();
                if (slot[ti & 31] >= remK) hi = mid; else lo = mid + 1;
                ti++;
                if ((ti & 31) == 0) {
                    __syncthreads();
                    if (tid < 32) slot[tid] = 0;
                    __syncthreads();
                }
            }
            tieCut = (uint32_t)lo;
        }

        // final scatter over the zeros (ordered behind zero stores by barriers)
        for (int i = 0; i < VPT; i++) {
            float4 v = xrow[tid + i * NT];
            const uint32_t col0 = (uint32_t)(tid + i * NT) * 4u;
            const uint32_t k0 = f2key(__float_as_uint(v.x));
            const uint32_t k1 = f2key(__float_as_uint(v.y));
            const uint32_t k2 = f2key(__float_as_uint(v.z));
            const uint32_t k3 = f2key(__float_as_uint(v.w));
            if (k0 > T || (k0 == T && col0 + 0u <= tieCut)) out[rowOff + col0 + 0] = key2f(k0);
            if (k1 > T || (k1 == T && col0 + 1u <= tieCut)) out[rowOff + col0 + 1] = key2f(k1);
            if (k2 > T || (k2 == T && col0 + 2u <= tieCut)) out[rowOff + col0 + 2] = key2f(k2);
            if (k3 > T || (k3 == T && col0 + 3u <= tieCut)) out[rowOff + col0 + 3] = key2f(k3);
        }
    }
}

extern "C" void kernel_launch(void* const* d_in, const int* in_sizes, int n_in,
                              void* d_out, int out_size)
{
    const float* x = (const float*)d_in[0];
    float* out = (float*)d_out;
    (void)in_sizes; (void)n_in; (void)out_size;

    topk_scatter_kernel<<<NROWS, NT>>>(x, out);
}

// round 6
// speedup vs baseline: 1.9971x; 1.3298x over previous
#include <cuda_runtime.h>
#include <stdint.h>

// TopK_31877247271346: per-row top-64 of x[4096][16384] fp32 scattered into zeros.
// One CTA (512 threads) per row, streaming:
//  - read row once, write full-row zeros immediately
//  - SIMD candidate detection (raw bits >= 0x40000000 signed, i.e. x >= 2.0):
//    PRMT top-byte pack + vsetges4 + dp4a -> 32-bit positional mask/thread
//  - warp-aggregated compaction of ~373 candidates into SMEM (raw bits = keys,
//    since all candidates are positive floats)
//  - exact 4-round radix select over candidates, stable lowest-index tie-break
//  - scatter <=64 winners over the zeros
// Exact key-space fallback via global re-reads if count outside [K, CAP].

#define NROWS 4096
#define NCOLS 16384
#define KSEL  64
#define NT    512
#define VPT   8
#define CAP   2048

__device__ __forceinline__ uint32_t f2key(uint32_t a) {
    return (a & 0x80000000u) ? ~a : (a | 0x80000000u);
}
__device__ __forceinline__ float key2f(uint32_t u) {
    return __uint_as_float((u & 0x80000000u) ? (u ^ 0x80000000u) : ~u);
}

__global__ void __launch_bounds__(NT, 4)
topk_scatter_kernel(const float* __restrict__ x, float* __restrict__ out)
{
    __shared__ uint32_t hist[256];
    __shared__ uint32_t bcast[3];     // prefix, remK, cntEq
    __shared__ uint32_t slot[32];     // per-iteration counters
    __shared__ uint32_t nCandS;
    __shared__ uint32_t skey[CAP];
    __shared__ uint16_t scol[CAP];

    const int tid  = threadIdx.x;
    const int lane = tid & 31;
    const size_t rowOff = (size_t)blockIdx.x * NCOLS;
    const uint4* __restrict__ xrow4 = reinterpret_cast<const uint4*>(x + rowOff);
    uint4* __restrict__ orow = reinterpret_cast<uint4*>(out + rowOff);

    // ---- batch-0 loads in flight while smem is initialized ----
    uint4 v[4];
    #pragma unroll
    for (int i = 0; i < 4; i++) v[i] = xrow4[tid + i * NT];

    if (tid < 256) hist[tid] = 0;
    if (tid < 32)  slot[tid] = 0;
    if (tid == 0)  nCandS = 0;
    __syncthreads();

    // ---- full-row zero stores (data-independent, hides load latency) ----
    const uint4 z4 = make_uint4(0u, 0u, 0u, 0u);
    #pragma unroll
    for (int i = 0; i < VPT; i++) orow[tid + i * NT] = z4;

    // ---- SIMD candidate mask: bit (g*4+c) set iff element is >= 2.0f ----
    uint32_t m = 0;
    #pragma unroll
    for (int i = 0; i < 4; i++) {
        uint32_t p01 = __byte_perm(v[i].x, v[i].y, 0x0073);
        uint32_t p23 = __byte_perm(v[i].z, v[i].w, 0x0073);
        uint32_t pb  = __byte_perm(p01, p23, 0x5410);     // top bytes of 4 elems
        uint32_t nib = __dp4a(__vsetges4(pb, 0x40404040u), 0x08040201u, 0u);
        m |= nib << (4 * i);
    }
    #pragma unroll
    for (int i = 0; i < 4; i++) v[i] = xrow4[tid + (4 + i) * NT];   // batch 1
    #pragma unroll
    for (int i = 0; i < 4; i++) {
        uint32_t p01 = __byte_perm(v[i].x, v[i].y, 0x0073);
        uint32_t p23 = __byte_perm(v[i].z, v[i].w, 0x0073);
        uint32_t pb  = __byte_perm(p01, p23, 0x5410);
        uint32_t nib = __dp4a(__vsetges4(pb, 0x40404040u), 0x08040201u, 0u);
        m |= nib << (16 + 4 * i);
    }

    // ---- warp-aggregated compaction (1 atomic per warp) ----
    {
        const uint32_t c = (uint32_t)__popc(m);
        uint32_t pre = c;
        #pragma unroll
        for (int off = 1; off < 32; off <<= 1) {
            uint32_t t = __shfl_up_sync(0xFFFFFFFFu, pre, off);
            if (lane >= off) pre += t;
        }
        uint32_t wbase = 0;
        if (lane == 31 && pre) wbase = atomicAdd(&nCandS, pre);
        wbase = __shfl_sync(0xFFFFFFFFu, wbase, 31);
        uint32_t base = wbase + (pre - c);

        uint32_t mm = m;
        while (mm) {
            const int e = __ffs(mm) - 1; mm &= mm - 1;
            const int g = e >> 2, cc = e & 3;
            const uint32_t col = (uint32_t)(tid + g * NT) * 4u + (uint32_t)cc;
            if (base < CAP) {
                skey[base] = __float_as_uint(__ldg(x + rowOff + col));  // L2 hit
                scol[base] = (uint16_t)col;
            }
            base++;
        }
    }
    __syncthreads();
    const uint32_t nc = nCandS;

    if (nc >= KSEL && nc <= CAP) {
        // ---- exact radix over candidates (raw bits; all positive floats) ----
        uint32_t prefix = 0, remK = KSEL, cntEq = 0;
        #pragma unroll 1
        for (int shift = 24; shift >= 0; shift -= 8) {
            const uint32_t pmask = (shift == 24) ? 0u : (0xFFFFFFFFu << (shift + 8));
            for (int j = tid; j < (int)nc; j += NT) {
                const uint32_t u = skey[j];
                if ((u & pmask) == prefix)
                    atomicAdd(&hist[(u >> shift) & 255u], 1u);
            }
            __syncthreads();

            if (tid < 32) {   // warp 0: suffix scan over 256 buckets, pick, re-zero
                uint32_t local[8], sum = 0;
                #pragma unroll
                for (int j = 0; j < 8; j++) { local[j] = hist[lane*8 + j]; sum += local[j]; }
                #pragma unroll
                for (int j = 0; j < 8; j++) hist[lane*8 + j] = 0;

                uint32_t tot = sum;
                #pragma unroll
                for (int off = 1; off < 32; off <<= 1) {
                    uint32_t t = __shfl_down_sync(0xFFFFFFFFu, tot, off);
                    if (lane + off < 32) tot += t;
                }
                uint32_t run = tot - sum;
                #pragma unroll
                for (int j = 7; j >= 0; j--) {
                    const uint32_t inc = run + local[j];
                    if (inc >= remK && run < remK) {
                        bcast[0] = prefix | ((uint32_t)(lane*8 + j) << shift);
                        bcast[1] = remK - run;
                        bcast[2] = local[j];
                    }
                    run = inc;
                }
            }
            __syncthreads();
            prefix = bcast[0];
            remK   = bcast[1];
            cntEq  = bcast[2];
        }
        const uint32_t T = prefix;

        // ---- stable lowest-index tie-break (rare) ----
        uint32_t tieCut = 0xFFFFFFFFu;
        if (cntEq != remK) {
            int lo = 0, hi = NCOLS - 1, it = 0;
            while (lo < hi) {                 // <=14 iters, slot[] pre-zeroed
                const int mid = (lo + hi) >> 1;
                uint32_t c = 0;
                for (int j = tid; j < (int)nc; j += NT)
                    c += (skey[j] == T && (int)scol[j] <= mid) ? 1u : 0u;
                #pragma unroll
                for (int off = 16; off >= 1; off >>= 1)
                    c += __shfl_down_sync(0xFFFFFFFFu, c, off);
                if (lane == 0 && c) atomicAdd(&slot[it], c);
                __syncthreads();
                if (slot[it] >= remK) hi = mid; else lo = mid + 1;
                it++;
            }
            tieCut = (uint32_t)lo;
        }

        // ---- scatter winners over the zeros (same-CTA order via barriers) ----
        for (int j = tid; j < (int)nc; j += NT) {
            const uint32_t u = skey[j];
            const uint32_t col = scol[j];
            if (u > T || (u == T && col <= tieCut))
                out[rowOff + col] = __uint_as_float(u);
        }
        return;
    }

    // ================= FALLBACK (exact, key-space, via global re-reads) ======
    {
        const float4* __restrict__ xrow = reinterpret_cast<const float4*>(x + rowOff);
        __syncthreads();
        if (tid < 32) slot[tid] = 0;
        __syncthreads();

        unsigned long long blo = 0ull, bhi = 0x100000000ull;
        int it = 0;
        while (bhi - blo > 1ull) {
            const uint32_t mid = (uint32_t)((blo + bhi) >> 1);
            uint32_t c = 0;
            for (int i = 0; i < VPT; i++) {
                float4 vv = xrow[tid + i * NT];
                c += (f2key(__float_as_uint(vv.x)) >= mid);
                c += (f2key(__float_as_uint(vv.y)) >= mid);
                c += (f2key(__float_as_uint(vv.z)) >= mid);
                c += (f2key(__float_as_uint(vv.w)) >= mid);
            }
            #pragma unroll
            for (int off = 16; off >= 1; off >>= 1)
                c += __shfl_down_sync(0xFFFFFFFFu, c, off);
            if (lane == 0 && c) atomicAdd(&slot[it & 31], c);
            __syncthreads();
            if (slot[it & 31] >= KSEL) blo = (unsigned long long)mid;
            else                       bhi = (unsigned long long)mid;
            it++;
            if ((it & 31) == 0) {
                __syncthreads();
                if (tid < 32) slot[tid] = 0;
                __syncthreads();
            }
        }
        const uint32_t T = (uint32_t)blo;

        __syncthreads();
        if (tid < 32) slot[tid] = 0;
        __syncthreads();
        {
            uint32_t ca = 0, ce = 0;
            for (int i = 0; i < VPT; i++) {
                float4 vv = xrow[tid + i * NT];
                const uint32_t k0 = f2key(__float_as_uint(vv.x));
                const uint32_t k1 = f2key(__float_as_uint(vv.y));
                const uint32_t k2 = f2key(__float_as_uint(vv.z));
                const uint32_t k3 = f2key(__float_as_uint(vv.w));
                ca += (k0 > T) + (k1 > T) + (k2 > T) + (k3 > T);
                ce += (k0 == T) + (k1 == T) + (k2 == T) + (k3 == T);
            }
            #pragma unroll
            for (int off = 16; off >= 1; off >>= 1) {
                ca += __shfl_down_sync(0xFFFFFFFFu, ca, off);
                ce += __shfl_down_sync(0xFFFFFFFFu, ce, off);
            }
            if (lane == 0) { atomicAdd(&slot[0], ca); atomicAdd(&slot[1], ce); }
        }
        __syncthreads();
        const uint32_t abv  = slot[0];
        const uint32_t eq   = slot[1];
        const uint32_t remK = KSEL - abv;

        uint32_t tieCut = 0xFFFFFFFFu;
        if (eq != remK) {
            __syncthreads();
            if (tid < 32) slot[tid] = 0;
            __syncthreads();
            int lo = 0, hi = NCOLS - 1, ti = 0;
            while (lo < hi) {
                const int mid = (lo + hi) >> 1;
                uint32_t c = 0;
                for (int i = 0; i < VPT; i++) {
                    float4 vv = xrow[tid + i * NT];
                    const int col0 = (tid + i * NT) * 4;
                    c += (f2key(__float_as_uint(vv.x)) == T && col0 + 0 <= mid);
                    c += (f2key(__float_as_uint(vv.y)) == T && col0 + 1 <= mid);
                    c += (f2key(__float_as_uint(vv.z)) == T && col0 + 2 <= mid);
                    c += (f2key(__float_as_uint(vv.w)) == T && col0 + 3 <= mid);
                }
                #pragma unroll
                for (int off = 16; off >= 1; off >>= 1)
                    c += __shfl_down_sync(0xFFFFFFFFu, c, off);
                if (lane == 0 && c) atomicAdd(&slot[ti & 31], c);
                __syncthreads();
                if (slot[ti & 31] >= remK) hi = mid; else lo = mid + 1;
                ti++;
                if ((ti & 31) == 0) {
                    __syncthreads();
                    if (tid < 32) slot[tid] = 0;
                    __syncthreads();
                }
            }
            tieCut = (uint32_t)lo;
        }

        for (int i = 0; i < VPT; i++) {
            float4 vv = xrow[tid + i * NT];
            const uint32_t col0 = (uint32_t)(tid + i * NT) * 4u;
            const uint32_t k0 = f2key(__float_as_uint(vv.x));
            const uint32_t k1 = f2key(__float_as_uint(vv.y));
            const uint32_t k2 = f2key(__float_as_uint(vv.z));
            const uint32_t k3 = f2key(__float_as_uint(vv.w));
            if (k0 > T || (k0 == T && col0 + 0u <= tieCut)) out[rowOff + col0 + 0] = key2f(k0);
            if (k1 > T || (k1 == T && col0 + 1u <= tieCut)) out[rowOff + col0 + 1] = key2f(k1);
            if (k2 > T || (k2 == T && col0 + 2u <= tieCut)) out[rowOff + col0 + 2] = key2f(k2);
            if (k3 > T || (k3 == T && col0 + 3u <= tieCut)) out[rowOff + col0 + 3] = key2f(k3);
        }
    }
}

extern "C" void kernel_launch(void* const* d_in, const int* in_sizes, int n_in,
                              void* d_out, int out_size)
{
    const float* x = (const float*)d_in[0];
    float* out = (float*)d_out;
    (void)in_sizes; (void)n_in; (void)out_size;

    topk_scatter_kernel<<<NROWS, NT>>>(x, out);
}